// round 2
// baseline (speedup 1.0000x reference)
#include <cuda_runtime.h>
#include <cuda_bf16.h>
#include <math.h>

#define BATCH 16
#define NCLS  6
#define HWPX  (512 * 512)
#define NPIX  (BATCH * HWPX)

#define SMOOTH_NR 1e-5
#define SMOOTH_DR 1e-5

// Global scratch accumulators (allocation-free rule: __device__ globals)
__device__ double d_inter[BATCH * NCLS];
__device__ double d_pred[BATCH * NCLS];
__device__ unsigned int d_ground[BATCH * NCLS];
__device__ double d_ce;

__global__ void gdl_init_kernel() {
    int i = threadIdx.x;
    if (i < BATCH * NCLS) {
        d_inter[i] = 0.0;
        d_pred[i] = 0.0;
        d_ground[i] = 0u;
    }
    if (i == 0) d_ce = 0.0;
}

// 256 threads/block, 4 pixels/thread -> 1024 pixels/block.
// HW=262144 -> 256 blocks per image, grid = 16*256 = 4096 blocks.
__global__ __launch_bounds__(256) void gdl_main_kernel(
    const float* __restrict__ logits,
    const int* __restrict__ labels)
{
    const int blocksPerImage = HWPX / 1024;          // 256
    const int b = blockIdx.x / blocksPerImage;
    const int hw0 = (blockIdx.x % blocksPerImage) * 1024 + threadIdx.x * 4;

    const float* base = logits + (size_t)b * NCLS * HWPX;

    // Load 4 pixels x 6 classes (6 coalesced float4 streams)
    float v[NCLS][4];
#pragma unroll
    for (int c = 0; c < NCLS; c++) {
        float4 x = *reinterpret_cast<const float4*>(base + (size_t)c * HWPX + hw0);
        v[c][0] = x.x; v[c][1] = x.y; v[c][2] = x.z; v[c][3] = x.w;
    }
    // Labels are int32 (JAX x64 disabled downcasts int64 -> int32)
    int4 lb = *reinterpret_cast<const int4*>(labels + (size_t)b * HWPX + hw0);
    int lab[4];
    lab[0] = lb.x; lab[1] = lb.y; lab[2] = lb.z; lab[3] = lb.w;

    float acc_pred[NCLS];
    float acc_inter[NCLS];
    int   acc_cnt[NCLS];
    float acc_ce = 0.0f;
#pragma unroll
    for (int c = 0; c < NCLS; c++) { acc_pred[c] = 0.0f; acc_inter[c] = 0.0f; acc_cnt[c] = 0; }

#pragma unroll
    for (int j = 0; j < 4; j++) {
        float m = v[0][j];
#pragma unroll
        for (int c = 1; c < NCLS; c++) m = fmaxf(m, v[c][j]);
        float e[NCLS];
        float s = 0.0f;
#pragma unroll
        for (int c = 0; c < NCLS; c++) { e[c] = __expf(v[c][j] - m); s += e[c]; }
        float inv = __frcp_rn(s);

        int l = lab[j];
        bool valid = (l >= 0) && (l < NCLS);

        float xl = 0.0f;  // logit of label class
#pragma unroll
        for (int c = 0; c < NCLS; c++) {
            float p = e[c] * inv;
            acc_pred[c] += p;
            bool isl = valid && (l == c);
            acc_inter[c] += isl ? p : 0.0f;
            acc_cnt[c] += isl ? 1 : 0;
            xl = isl ? v[c][j] : xl;
        }
        // ce = -(x_l - m - log(s)) for valid pixels
        acc_ce += valid ? (__logf(s) - (xl - m)) : 0.0f;
    }

    // Warp reduction
    const unsigned FULL = 0xFFFFFFFFu;
#pragma unroll
    for (int off = 16; off > 0; off >>= 1) {
#pragma unroll
        for (int c = 0; c < NCLS; c++) {
            acc_pred[c]  += __shfl_down_sync(FULL, acc_pred[c],  off);
            acc_inter[c] += __shfl_down_sync(FULL, acc_inter[c], off);
            acc_cnt[c]   += __shfl_down_sync(FULL, acc_cnt[c],   off);
        }
        acc_ce += __shfl_down_sync(FULL, acc_ce, off);
    }

    __shared__ float s_pred[8][NCLS];
    __shared__ float s_inter[8][NCLS];
    __shared__ int   s_cnt[8][NCLS];
    __shared__ float s_ce[8];

    int wid = threadIdx.x >> 5;
    int lid = threadIdx.x & 31;
    if (lid == 0) {
#pragma unroll
        for (int c = 0; c < NCLS; c++) {
            s_pred[wid][c]  = acc_pred[c];
            s_inter[wid][c] = acc_inter[c];
            s_cnt[wid][c]   = acc_cnt[c];
        }
        s_ce[wid] = acc_ce;
    }
    __syncthreads();

    // Cross-warp: threads 0..5 handle one class each; thread 6 handles CE.
    if (threadIdx.x < NCLS) {
        int c = threadIdx.x;
        float pr = 0.0f, in = 0.0f;
        int cn = 0;
#pragma unroll
        for (int w = 0; w < 8; w++) {
            pr += s_pred[w][c];
            in += s_inter[w][c];
            cn += s_cnt[w][c];
        }
        int idx = b * NCLS + c;
        atomicAdd(&d_pred[idx], (double)pr);
        atomicAdd(&d_inter[idx], (double)in);
        atomicAdd(&d_ground[idx], (unsigned int)cn);
    } else if (threadIdx.x == NCLS) {
        float ce = 0.0f;
#pragma unroll
        for (int w = 0; w < 8; w++) ce += s_ce[w];
        atomicAdd(&d_ce, (double)ce);
    }
}

__global__ void gdl_final_kernel(float* out) {
    if (threadIdx.x != 0 || blockIdx.x != 0) return;

    double num_s[NCLS];
    double den_s[NCLS];
    for (int c = 0; c < NCLS; c++) { num_s[c] = 0.0; den_s[c] = 0.0; }

    for (int b = 0; b < BATCH; b++) {
        double w[NCLS];
        bool is_inf[NCLS];
        double rowmax = 0.0;
        for (int c = 0; c < NCLS; c++) {
            double g = (double)d_ground[b * NCLS + c];
            if (g == 0.0) {
                is_inf[c] = true;
                w[c] = 0.0;
            } else {
                is_inf[c] = false;
                w[c] = 1.0 / (g * g);
                if (w[c] > rowmax) rowmax = w[c];
            }
        }
        for (int c = 0; c < NCLS; c++) {
            double ww = is_inf[c] ? rowmax : w[c];
            double g = (double)d_ground[b * NCLS + c];
            num_s[c] += d_inter[b * NCLS + c] * ww;
            den_s[c] += (g + d_pred[b * NCLS + c]) * ww;
        }
    }

    double fmean = 0.0;
    for (int c = 0; c < NCLS; c++) {
        double f = 1.0 - (2.0 * num_s[c] + SMOOTH_NR) / (den_s[c] + SMOOTH_DR);
        fmean += f;
    }
    fmean /= (double)NCLS;

    double pixel_loss = d_ce / (double)NPIX;
    out[0] = (float)(fmean + pixel_loss);
}

extern "C" void kernel_launch(void* const* d_in, const int* in_sizes, int n_in,
                              void* d_out, int out_size) {
    const float* logits = (const float*)d_in[0];
    const int* labels = (const int*)d_in[1];
    float* out = (float*)d_out;

    gdl_init_kernel<<<1, 128>>>();
    gdl_main_kernel<<<NPIX / 1024, 256>>>(logits, labels);
    gdl_final_kernel<<<1, 32>>>(out);
}